// round 14
// baseline (speedup 1.0000x reference)
#include <cuda_runtime.h>
#include <cstddef>

// B=2, N=4096, K=48, Q=20
// inputs : d_in[0]=S (i32), d_in[1]=h (f32), d_in[2]=J (f32), d_in[3]=edge_idx (i32)
// output : d_out = [ U (B) | U_i (B*N*Q) ] fp32
//
// Final converged design (best-measured over 6 structural variants):
// dense (group,q) thread mapping, 48-deep __ldcs gather with 4 accumulators,
// fused last-block U reduction. DRAM traffic is pinned at the full J tensor
// (128B fill granularity vs the 80B gather stride) and every design variant
// measures 6.5-6.8 TB/s => this sits at the chip's bandwidth floor.

namespace {
constexpr int Bc = 2;
constexpr int Nc = 4096;
constexpr int Kc = 48;
constexpr int Qc = 20;
constexpr int GPB = 16;                 // groups per block
constexpr int TPB = GPB * Qc;           // 320 threads = 10 full warps
constexpr int GROUPS = Bc * Nc;         // 8192
constexpr int NBLK = GROUPS / GPB;      // 512
constexpr int BLK_PER_B = NBLK / Bc;    // 256
}

__device__ float g_partial[NBLK];
__device__ int   g_count = 0;           // self-resetting epoch counter

__global__ __launch_bounds__(TPB)
void potts_fused_kernel(const int* __restrict__ S,
                        const float* __restrict__ h,
                        const float* __restrict__ J,
                        const int* __restrict__ eidx,
                        float* __restrict__ out)
{
    const int tid   = threadIdx.x;
    const int gl    = tid / Qc;                 // 0..15
    const int q     = tid - gl * Qc;            // 0..19
    const int group = blockIdx.x * GPB + gl;

    __shared__ int   s_sh[GPB][Kc];
    __shared__ float c_sh[GPB];
    __shared__ float red[BLK_PER_B];
    __shared__ bool  is_last;

    // Gather this block's 16*48 neighbor states (S: 32 KB, L2-resident).
    const int ebase = blockIdx.x * GPB * Kc;
    #pragma unroll
    for (int t = tid; t < GPB * Kc; t += TPB) {
        const int g_of = t / Kc;
        const int k_of = t - g_of * Kc;
        const int grp  = blockIdx.x * GPB + g_of;
        const int b_of = grp >> 12;
        s_sh[g_of][k_of] = S[b_of * Nc + eidx[ebase + t]];
    }
    __syncthreads();

    // Row pointer for this q: J[group][k][q][*], stride Q*Q floats per k.
    const float* Jg   = J + (size_t)group * (Kc * Qc * Qc) + (size_t)q * Qc;
    const int*   srow = s_sh[gl];

    float a0 = 0.f, a1 = 0.f, a2 = 0.f, a3 = 0.f;
    #pragma unroll
    for (int k = 0; k < Kc; k += 4) {
        a0 += __ldcs(Jg + (size_t)(k + 0) * (Qc * Qc) + srow[k + 0]);
        a1 += __ldcs(Jg + (size_t)(k + 1) * (Qc * Qc) + srow[k + 1]);
        a2 += __ldcs(Jg + (size_t)(k + 2) * (Qc * Qc) + srow[k + 2]);
        a3 += __ldcs(Jg + (size_t)(k + 3) * (Qc * Qc) + srow[k + 3]);
    }
    const float ji = (a0 + a1) + (a2 + a3);
    const float hv = h[(size_t)group * Qc + q];
    const float ui = hv + ji;
    out[Bc + (size_t)group * Qc + q] = ui;

    // Per-group U contribution: 0.5*(U_i[s]+h[s]) at s = S[group].
    if (q == S[group]) {
        c_sh[gl] = 0.5f * (ui + hv);
    }
    __syncthreads();

    // Per-block partial + epoch counter (threadFenceReduction pattern).
    if (tid == 0) {
        float s = 0.f;
        #pragma unroll
        for (int g = 0; g < GPB; g++) s += c_sh[g];
        g_partial[blockIdx.x] = s;
        __threadfence();
        is_last = (atomicAdd(&g_count, 1) == NBLK - 1);
    }
    __syncthreads();

    if (is_last) {
        // Deterministic tree reduction of the 256 partials per batch.
        #pragma unroll
        for (int b = 0; b < Bc; b++) {
            if (tid < BLK_PER_B) red[tid] = g_partial[b * BLK_PER_B + tid];
            __syncthreads();
            #pragma unroll
            for (int st = BLK_PER_B / 2; st > 0; st >>= 1) {
                if (tid < st) red[tid] += red[tid + st];
                __syncthreads();
            }
            if (tid == 0) out[b] = red[0];
            __syncthreads();
        }
        if (tid == 0) g_count = 0;   // reset for next graph replay
    }
}

extern "C" void kernel_launch(void* const* d_in, const int* in_sizes, int n_in,
                              void* d_out, int out_size)
{
    const int*   S    = (const int*)  d_in[0];
    const float* h    = (const float*)d_in[1];
    const float* J    = (const float*)d_in[2];
    const int*   eidx = (const int*)  d_in[3];
    float*       out  = (float*)      d_out;

    potts_fused_kernel<<<NBLK, TPB>>>(S, h, J, eidx, out);

    (void)in_sizes; (void)n_in; (void)out_size;
}

// round 15
// speedup vs baseline: 1.0104x; 1.0104x over previous
#include <cuda_runtime.h>
#include <cstdint>
#include <cstddef>

// B=2, N=4096, K=48, Q=20
// inputs : d_in[0]=S (i32), d_in[1]=h (f32), d_in[2]=J (f32), d_in[3]=edge_idx (i32)
// output : d_out = [ U (B) | U_i (B*N*Q) ] fp32
//
// CONVERGED DESIGN (best kernel time 93.98us / DRAM 85.3% across 7 variants):
// DRAM traffic is pinned at the full J tensor (128B L2->DRAM fetch granularity
// vs the 80B gather stride; measured 635MB on every load-path variant), so the
// optimal kernel is a coalesced cp.async stream of J into a 2-stage smem
// double buffer with the column-select done from smem, fused with the U
// reduction via a last-block epoch counter.

namespace {
constexpr int Bc = 2;
constexpr int Nc = 4096;
constexpr int Kc = 48;
constexpr int Qc = 20;
constexpr int MAT = Qc * Qc;              // 400 floats per (g,k) matrix
constexpr int G   = 2;                    // groups per block
constexpr int KCH = 4;                    // k-matrices per chunk
constexpr int NCH = Kc / KCH;             // 12 chunks
constexpr int TPB = G * Qc * KCH;         // 160 threads = (g, q, kk)
constexpr int CHUNK_FLOATS = G * KCH * MAT;      // 3200 (12.8 KB)
constexpr int CHUNK_V4     = CHUNK_FLOATS / 4;   // 800 float4
constexpr int VPT          = CHUNK_V4 / TPB;     // 5 float4 per thread/chunk
constexpr int GROUPS = Bc * Nc;           // 8192
constexpr int NBLK   = GROUPS / G;        // 4096
constexpr int BLK_PER_B = NBLK / Bc;      // 2048
}

__device__ float g_partial[NBLK];
__device__ int   g_count = 0;             // self-resetting epoch counter

__device__ __forceinline__ unsigned smem_addr(const void* p) {
    return (unsigned)__cvta_generic_to_shared(p);
}
__device__ __forceinline__ void cp16(unsigned dst, const float4* src) {
    asm volatile("cp.async.cg.shared.global [%0], [%1], 16;" :: "r"(dst), "l"(src));
}
__device__ __forceinline__ void cp_commit() {
    asm volatile("cp.async.commit_group;");
}
template <int N>
__device__ __forceinline__ void cp_wait() {
    asm volatile("cp.async.wait_group %0;" :: "n"(N));
}

__global__ __launch_bounds__(TPB)
void potts_stream_kernel(const int* __restrict__ S,
                         const float* __restrict__ h,
                         const float* __restrict__ J,
                         const int* __restrict__ eidx,
                         float* __restrict__ out)
{
    __shared__ float Jsh[2][CHUNK_FLOATS];        // 25.6 KB double buffer
    __shared__ int   s_sh[G][Kc];
    __shared__ float part[G][Qc][KCH];
    __shared__ float c_sh[G];
    __shared__ bool  is_last;

    const int tid   = threadIdx.x;
    const int gbase = blockIdx.x * G;

    // Loader mapping (constant across chunks): float4 f = tid + i*TPB,
    // gg = f/400, rem = f%400 within the group's chunk slice.
    int      l_gg[VPT], l_rem[VPT];
    unsigned l_dst0[VPT];
    const float4* Jv4 = (const float4*)J;
    #pragma unroll
    for (int i = 0; i < VPT; i++) {
        const int f = tid + i * TPB;
        l_gg[i]  = f / (KCH * MAT / 4);
        l_rem[i] = f - l_gg[i] * (KCH * MAT / 4);
        l_dst0[i] = smem_addr(&Jsh[0][l_gg[i] * KCH * MAT + l_rem[i] * 4]);
    }
    #define ISSUE_CHUNK(c, buf)                                                   \
        do {                                                                      \
            _Pragma("unroll")                                                     \
            for (int i = 0; i < VPT; i++) {                                       \
                const float4* src = Jv4                                           \
                    + (size_t)(gbase + l_gg[i]) * (Kc * MAT / 4)                  \
                    + (size_t)(c) * (KCH * MAT / 4) + l_rem[i];                   \
                cp16(l_dst0[i] + (buf) * (CHUNK_FLOATS * 4), src);                \
            }                                                                     \
            cp_commit();                                                          \
        } while (0)

    // Prime the pipeline, then gather neighbor states (overlaps async loads).
    ISSUE_CHUNK(0, 0);
    ISSUE_CHUNK(1, 1);

    for (int t = tid; t < G * Kc; t += TPB) {
        const int gg = t / Kc, k = t - gg * Kc;
        const int grp = gbase + gg;
        const int b   = grp >> 12;
        s_sh[gg][k] = S[b * Nc + eidx[(size_t)grp * Kc + k]];
    }

    // Compute mapping: tid = (cg, cq, ck)
    const int cg = tid / (Qc * KCH);
    const int r  = tid - cg * (Qc * KCH);
    const int cq = r / KCH;
    const int ck = r - cq * KCH;
    const int smem_base_idx = cg * KCH * MAT + ck * MAT + cq * Qc;

    float acc = 0.f;
    #pragma unroll
    for (int c = 0; c < NCH; c++) {
        if (c < NCH - 1) cp_wait<1>(); else cp_wait<0>();
        __syncthreads();                           // chunk c visible to all
        const float* buf = Jsh[c & 1];
        acc += buf[smem_base_idx + s_sh[cg][c * KCH + ck]];
        __syncthreads();                           // done reading buf[c&1]
        if (c + 2 < NCH) ISSUE_CHUNK(c + 2, c & 1);
    }
    #undef ISSUE_CHUNK

    part[cg][cq][ck] = acc;
    __syncthreads();

    if (tid < G * Qc) {
        const int gg  = tid / Qc, q = tid - gg * Qc;
        const int grp = gbase + gg;
        const float ji = (part[gg][q][0] + part[gg][q][1])
                       + (part[gg][q][2] + part[gg][q][3]);
        const float hv = h[(size_t)grp * Qc + q];
        const float ui = hv + ji;
        out[Bc + (size_t)grp * Qc + q] = ui;
        if (q == S[grp]) c_sh[gg] = 0.5f * (ui + hv);
    }
    __syncthreads();

    if (tid == 0) {
        g_partial[blockIdx.x] = c_sh[0] + c_sh[1];
        __threadfence();
        is_last = (atomicAdd(&g_count, 1) == NBLK - 1);
    }
    __syncthreads();

    if (is_last) {
        float* red = &Jsh[0][0];                  // reuse streaming buffer
        #pragma unroll
        for (int b = 0; b < Bc; b++) {
            float s = 0.f;
            for (int i = tid; i < BLK_PER_B; i += TPB)
                s += g_partial[b * BLK_PER_B + i];
            red[tid] = s;
            __syncthreads();
            if (tid == 0) {
                float t = 0.f;
                #pragma unroll
                for (int i = 0; i < TPB; i++) t += red[i];
                out[b] = t;
            }
            __syncthreads();
        }
        if (tid == 0) g_count = 0;                // reset for next replay
    }
}

extern "C" void kernel_launch(void* const* d_in, const int* in_sizes, int n_in,
                              void* d_out, int out_size)
{
    const int*   S    = (const int*)  d_in[0];
    const float* h    = (const float*)d_in[1];
    const float* J    = (const float*)d_in[2];
    const int*   eidx = (const int*)  d_in[3];
    float*       out  = (float*)      d_out;

    potts_stream_kernel<<<NBLK, TPB>>>(S, h, J, eidx, out);

    (void)in_sizes; (void)n_in; (void)out_size;
}